// round 11
// baseline (speedup 1.0000x reference)
#include <cuda_runtime.h>
#include <cstdint>
#include <math.h>

#define BB 64
#define TT 512
#define DD 512
#define UU 1024
#define G4 4096   // 4*UU
#define NBLK 128
#define NTHR 256

// Scratch (allocation-free rule: __device__ globals)
__device__ float g_xg[(size_t)TT * NBLK * BB * 32];  // [t][blk][row][g*8+j] = 512MB
__device__ float g_Wxtf[(size_t)DD * G4];            // tf32-rounded Wx (8MB)
// h ping-pong in FRAGMENT layout:
// gidx(u,row) = (((u>>6)*2 + ((u>>5)&1))*64 + row)*32 + (u&3)*8 + ((u&31)>>2)
__device__ float g_h[2 * BB * UU];
__device__ unsigned g_flag[NBLK];                    // per-block completed-step count

// ---------- helpers ----------
__device__ __forceinline__ unsigned f2tf(float x) {
    unsigned r;
    asm volatile("cvt.rna.tf32.f32 %0, %1;" : "=r"(r) : "f"(x));
    return r;
}
__device__ __forceinline__ float tfbits(float x) { return __uint_as_float(f2tf(x)); }
__device__ __forceinline__ unsigned fu(float x) { return __float_as_uint(x); }
__device__ __forceinline__ unsigned futf(float x) { return f2tf(x); }

__device__ __forceinline__ void mma_tf32(float d[4], const unsigned a[4], unsigned b0, unsigned b1) {
    asm volatile(
        "mma.sync.aligned.m16n8k8.row.col.f32.tf32.tf32.f32 "
        "{%0,%1,%2,%3}, {%4,%5,%6,%7}, {%8,%9}, {%0,%1,%2,%3};"
        : "+f"(d[0]), "+f"(d[1]), "+f"(d[2]), "+f"(d[3])
        : "r"(a[0]), "r"(a[1]), "r"(a[2]), "r"(a[3]), "r"(b0), "r"(b1));
}

__device__ __forceinline__ float fsig(float z) { return 1.f / (1.f + __expf(-z)); }
__device__ __forceinline__ float ftanh(float z) { return 2.f / (1.f + __expf(-2.f * z)) - 1.f; }

__device__ __forceinline__ void cp_async16(uint32_t s, const float* g) {
    asm volatile("cp.async.cg.shared.global [%0], [%1], 16;\n" :: "r"(s), "l"(g));
}
#define CP_COMMIT() asm volatile("cp.async.commit_group;\n" ::: "memory")
#define CP_WAIT(N)  asm volatile("cp.async.wait_group %0;\n" :: "n"(N) : "memory")

// fragment-layout index for h: u in [0,1024), row in [0,64)
__device__ __forceinline__ int h_gidx(int u, int row) {
    int chunk = u >> 6;
    int sub   = (u >> 5) & 1;
    int tig   = u & 3;
    int m     = (u & 31) >> 2;
    return (((chunk * 2 + sub) * 64) + row) * 32 + tig * 8 + m;
}

// ---------- Kernel 1: prep — tf32-round Wx; h0 -> g_h (fragment layout); clear flags ----------
__global__ void __launch_bounds__(256) prep(const float* __restrict__ h0,
                                            const float* __restrict__ Wx) {
    int idx = blockIdx.x * 256 + threadIdx.x;
    if (idx < DD * G4) g_Wxtf[idx] = tfbits(Wx[idx]);
    if (idx < BB * UU) {
        int row = idx >> 10;
        int u   = idx & (UU - 1);
        g_h[h_gidx(u, row)] = tfbits(h0[idx]);
    }
    if (idx < NBLK) g_flag[idx] = 0;
}

// ---------- Kernel 2: xg = x @ Wx + b (pipelined, 4-stage cp.async) — proven R9/R10 ----------
#define XA_ST (128 * 36)   // 4608 floats per A stage
#define XB_ST (32 * 68)    // 2176 floats per B stage
__global__ void __launch_bounds__(256, 2) xg_kernel(const float* __restrict__ x,
                                                    const float* __restrict__ bias) {
    extern __shared__ float sm[];
    float* As = sm;               // 4 stages
    float* Bs = sm + 4 * XA_ST;   // 4 stages

    const int tid  = threadIdx.x;
    const int w    = tid >> 5;
    const int lane = tid & 31;
    const int gid  = lane >> 2;
    const int tig  = lane & 3;
    const int wm   = w >> 1;
    const int wn   = w & 1;

    const int m0 = blockIdx.y * 128;
    const int c0 = blockIdx.x * 64;

    const uint32_t as_base = (uint32_t)__cvta_generic_to_shared(As);
    const uint32_t bs_base = (uint32_t)__cvta_generic_to_shared(Bs);

    float acc[2][4][4];
#pragma unroll
    for (int mi = 0; mi < 2; mi++)
#pragma unroll
        for (int ni = 0; ni < 4; ni++)
#pragma unroll
            for (int j = 0; j < 4; j++) acc[mi][ni][j] = 0.f;

    auto issue = [&](int kc, int s) {
#pragma unroll
        for (int i = 0; i < 4; i++) {
            int id  = tid + i * 256;
            int row = id >> 3;
            int k4  = (id & 7) * 4;
            cp_async16(as_base + (uint32_t)((s * XA_ST + row * 36 + k4) * 4),
                       x + (size_t)(m0 + row) * DD + kc * 32 + k4);
        }
#pragma unroll
        for (int i = 0; i < 2; i++) {
            int id = tid + i * 256;
            int k  = id >> 4;
            int n4 = (id & 15) * 4;
            cp_async16(bs_base + (uint32_t)((s * XB_ST + k * 68 + n4) * 4),
                       g_Wxtf + (size_t)(kc * 32 + k) * G4 + c0 + n4);
        }
    };

    issue(0, 0); CP_COMMIT();
    issue(1, 1); CP_COMMIT();
    issue(2, 2); CP_COMMIT();

    for (int kc = 0; kc < 16; kc++) {
        CP_WAIT(2);
        __syncthreads();
        if (kc + 3 < 16) issue(kc + 3, (kc + 3) & 3);
        CP_COMMIT();

        const float* A = As + (kc & 3) * XA_ST;
        const float* B = Bs + (kc & 3) * XB_ST;
#pragma unroll
        for (int q = 0; q < 4; q++) {
            const int kk = q * 8 + tig;
            unsigned a[2][4];
#pragma unroll
            for (int mi = 0; mi < 2; mi++) {
                int r0 = wm * 32 + mi * 16 + gid;
                a[mi][0] = futf(A[r0 * 36 + kk]);
                a[mi][1] = futf(A[(r0 + 8) * 36 + kk]);
                a[mi][2] = futf(A[r0 * 36 + kk + 4]);
                a[mi][3] = futf(A[(r0 + 8) * 36 + kk + 4]);
            }
#pragma unroll
            for (int ni = 0; ni < 4; ni++) {
                int cb = wn * 32 + ni * 8 + gid;
                unsigned b0 = fu(B[kk * 68 + cb]);
                unsigned b1 = fu(B[(kk + 4) * 68 + cb]);
#pragma unroll
                for (int mi = 0; mi < 2; mi++) mma_tf32(acc[mi][ni], a[mi], b0, b1);
            }
        }
        __syncthreads();
    }

#pragma unroll
    for (int mi = 0; mi < 2; mi++) {
#pragma unroll
        for (int ni = 0; ni < 4; ni++) {
#pragma unroll
            for (int j = 0; j < 4; j++) {
                int m   = m0 + wm * 32 + mi * 16 + gid + ((j >= 2) ? 8 : 0);
                int col = c0 + wn * 32 + ni * 8 + tig * 2 + (j & 1);
                float v = acc[mi][ni][j] + bias[col];
                int b   = m >> 9;
                int t   = m & (TT - 1);
                int g   = col >> 10;
                int u   = col & (UU - 1);
                int blk = u >> 3;
                int jj  = u & 7;
                g_xg[(((size_t)t * NBLK + blk) * BB + b) * 32 + g * 8 + jj] = v;
            }
        }
    }
}

// ---------- Kernel 3: persistent LSTM, K-split-4, DIRECT-LDG A fragments ----------
// 8 warps = 4 K-groups (kg = w>>1) x 2 row-halves (wm2 = w&1).
// A fragments stream straight from g_h (fragment layout) via LDG.128 with a
// 2-deep register double buffer. No h staging, no named barriers, no cp.async.
__global__ void __launch_bounds__(NTHR, 1) lstm_persistent(const float* __restrict__ Wh,
                                                           const float* __restrict__ c0,
                                                           float* __restrict__ out) {
    extern __shared__ float smem[];
    float* FB = smem;               // 32768 f: B-fragments (XOR-swizzled)
    float* GM = FB + 32768;         // 4*64*33 f: gate-partial exchange

    const int tid  = threadIdx.x;
    const int w    = tid >> 5;
    const int lane = tid & 31;
    const int gid  = lane >> 2;
    const int tig  = lane & 3;
    const int kg   = w >> 1;        // K-group 0..3
    const int wm2  = w & 1;         // row half
    const int blk  = blockIdx.x;
    const int u0   = blk * 8;

    // one-time: Wh fragments (tf32), XOR-swizzled float4 placement (proven R10)
    for (int idx = tid; idx < 32768; idx += NTHR) {
        int e     = idx & 7;
        int ln    = (idx >> 3) & 31;
        int f     = idx >> 8;            // kcc32*4 + tile
        int q     = e >> 1;
        int pair  = e & 1;
        int lgid  = ln >> 2;
        int ltig  = ln & 3;
        int kcc32 = f >> 2;
        int tile  = f & 3;
        int k     = kcc32 * 32 + q * 8 + ltig + pair * 4;
        int pidx  = ((f * 32 + ln) * 2 + ((e >> 2) ^ (lgid & 1))) * 4 + (e & 3);
        FB[pidx] = tfbits(Wh[(size_t)k * G4 + tile * UU + u0 + lgid]);
    }

    float creg[2];
#pragma unroll
    for (int i = 0; i < 2; i++) {
        int e = tid + i * NTHR;
        int row = e >> 3, j = e & 7;
        creg[i] = c0[(size_t)row * UU + u0 + j];
    }
    __syncthreads();

    const float4* FB4 = reinterpret_cast<const float4*>(FB);
    const int ch2 = (blk >> 3) * 2 + ((blk >> 2) & 1);   // epilogue h fragment constants
    volatile unsigned* vflag = (volatile unsigned*)g_flag;

    // per-thread A-fragment base offsets within a sub (64 rows * 32 floats)
    const int rA = wm2 * 32 + gid;        // mt=0 row
    const int rB = rA + 16;               // mt=1 row
    const int offA0 = rA * 32 + tig * 8;
    const int offA1 = (rA + 8) * 32 + tig * 8;
    const int offB0 = rB * 32 + tig * 8;
    const int offB1 = (rB + 8) * 32 + tig * 8;

    for (int t = 0; t < TT; t++) {
        const float* h_in = g_h + (size_t)(t & 1) * BB * UU;
        float* h_out      = g_h + (size_t)((t + 1) & 1) * BB * UU;
        const float* xgt  = g_xg + ((size_t)t * NBLK + blk) * (BB * 32);

        // ---- wait for ALL producers of h_t (single wide poll, proven) ----
        if (t > 0 && tid < NBLK) {
            while (vflag[tid] < (unsigned)t) { }
            __threadfence();
        }
        __syncthreads();   // also guards GM reuse across steps

        // xg prefetch into registers (consumed only in epilogue)
        float xr[2][4];
#pragma unroll
        for (int i = 0; i < 2; i++) {
            int e = tid + i * NTHR;
            int row = e >> 3, j = e & 7;
#pragma unroll
            for (int g = 0; g < 4; g++)
                xr[i][g] = __ldg(xgt + row * 32 + g * 8 + j);
        }

        float acc[2][4][4];
#pragma unroll
        for (int mt = 0; mt < 2; mt++)
#pragma unroll
            for (int tl = 0; tl < 4; tl++)
#pragma unroll
                for (int j = 0; j < 4; j++) acc[mt][tl][j] = 0.f;

        // A-fragment register double buffer: [buf][mt*4 + {A0,A1,B0,B1}]
        float4 abuf[2][8];
        auto loadA = [&](int s, float4* ab) {
            const float* g = h_in + (size_t)(kg * 8 + s) * 2048;
            ab[0] = *reinterpret_cast<const float4*>(g + offA0);
            ab[1] = *reinterpret_cast<const float4*>(g + offA0 + 4);
            ab[2] = *reinterpret_cast<const float4*>(g + offA1);
            ab[3] = *reinterpret_cast<const float4*>(g + offA1 + 4);
            ab[4] = *reinterpret_cast<const float4*>(g + offB0);
            ab[5] = *reinterpret_cast<const float4*>(g + offB0 + 4);
            ab[6] = *reinterpret_cast<const float4*>(g + offB1);
            ab[7] = *reinterpret_cast<const float4*>(g + offB1 + 4);
        };

        loadA(0, abuf[0]);

#pragma unroll
        for (int s = 0; s < 8; s++) {
            if (s < 7) loadA(s + 1, abuf[(s + 1) & 1]);

            const float4* ab = abuf[s & 1];
            const int kcc32 = kg * 8 + s;

            // build a-regs: per mt, fA0=ab[mt*4+0], fA1=ab[mt*4+1], fB0=ab[mt*4+2], fB1=ab[mt*4+3]
            unsigned a[2][4][4];
#pragma unroll
            for (int mt = 0; mt < 2; mt++) {
                float4 fA0 = ab[mt * 4 + 0];
                float4 fA1 = ab[mt * 4 + 1];
                float4 fB0 = ab[mt * 4 + 2];
                float4 fB1 = ab[mt * 4 + 3];
                a[mt][0][0] = fu(fA0.x); a[mt][0][1] = fu(fB0.x); a[mt][0][2] = fu(fA0.y); a[mt][0][3] = fu(fB0.y);
                a[mt][1][0] = fu(fA0.z); a[mt][1][1] = fu(fB0.z); a[mt][1][2] = fu(fA0.w); a[mt][1][3] = fu(fB0.w);
                a[mt][2][0] = fu(fA1.x); a[mt][2][1] = fu(fB1.x); a[mt][2][2] = fu(fA1.y); a[mt][2][3] = fu(fB1.y);
                a[mt][3][0] = fu(fA1.z); a[mt][3][1] = fu(fB1.z); a[mt][3][2] = fu(fA1.w); a[mt][3][3] = fu(fB1.w);
            }

#pragma unroll
            for (int tl = 0; tl < 4; tl++) {
                int bidx = ((kcc32 * 4 + tl) * 32 + lane) * 2;
                float4 b0v = FB4[bidx + (gid & 1)];
                float4 b1v = FB4[bidx + ((gid & 1) ^ 1)];
#pragma unroll
                for (int mt = 0; mt < 2; mt++) {
                    mma_tf32(acc[mt][tl], a[mt][0], fu(b0v.x), fu(b0v.y));
                    mma_tf32(acc[mt][tl], a[mt][1], fu(b0v.z), fu(b0v.w));
                    mma_tf32(acc[mt][tl], a[mt][2], fu(b1v.x), fu(b1v.y));
                    mma_tf32(acc[mt][tl], a[mt][3], fu(b1v.z), fu(b1v.w));
                }
            }
        }

        // write partials: GM[kg][row][col] (per-warp disjoint rows -> no pre-sync)
#pragma unroll
        for (int mt = 0; mt < 2; mt++)
#pragma unroll
            for (int tl = 0; tl < 4; tl++)
#pragma unroll
                for (int j = 0; j < 4; j++) {
                    int row = wm2 * 32 + mt * 16 + gid + ((j >> 1) ? 8 : 0);
                    int col = tl * 8 + tig * 2 + (j & 1);
                    GM[(kg * 64 + row) * 33 + col] = acc[mt][tl][j];
                }
        __syncthreads();

        // epilogue: sum 4 partials + xg, gates, c/h update
#pragma unroll
        for (int i = 0; i < 2; i++) {
            int e = tid + i * NTHR;
            int row = e >> 3, j = e & 7;
            float z[4];
#pragma unroll
            for (int g = 0; g < 4; g++) {
                float s = xr[i][g];
#pragma unroll
                for (int p = 0; p < 4; p++)
                    s += GM[(p * 64 + row) * 33 + g * 8 + j];
                z[g] = s;
            }
            float ig = fsig(z[0]);
            float fg = fsig(z[1]);
            float gg = ftanh(z[2]);
            float og = fsig(z[3]);

            creg[i] = fg * creg[i] + ig * gg;
            float hv = og * ftanh(creg[i]);
            if (t == TT - 1) {
                out[(size_t)row * UU + u0 + j] = hv;
            } else {
                int mv   = (blk & 3) * 2 + (j >> 2);
                int tigv = j & 3;
                h_out[(ch2 * 64 + row) * 32 + tigv * 8 + mv] = tfbits(hv);
            }
        }

        // publish completion
        __syncthreads();
        if (t + 1 < TT && tid == 0) {
            __threadfence();
            atomicExch(&g_flag[blk], (unsigned)(t + 1));
        }
    }
}

// ---------- launch (exactly 3 kernels: prep, xg, lstm) ----------
extern "C" void kernel_launch(void* const* d_in, const int* in_sizes, int n_in,
                              void* d_out, int out_size) {
    const float *x = nullptr, *h0 = nullptr, *c0 = nullptr;
    const float *Wx = nullptr, *Wh = nullptr, *bias = nullptr;
    for (int i = 0; i < n_in; i++) {
        const int s = in_sizes[i];
        const float* p = (const float*)d_in[i];
        if      (s == BB * TT * DD) x = p;
        else if (s == DD * G4)      Wx = p;
        else if (s == UU * G4)      Wh = p;
        else if (s == G4)           bias = p;
        else if (s == BB * UU)      { if (!h0) h0 = p; else c0 = p; }
    }

    const int XG_SMEM   = (4 * XA_ST + 4 * XB_ST) * 4;     // 108544
    const int LSTM_SMEM = (32768 + 4 * 64 * 33) * 4;       // 164864

    static bool attr_set = false;
    if (!attr_set) {
        cudaFuncSetAttribute(xg_kernel,
                             cudaFuncAttributeMaxDynamicSharedMemorySize, XG_SMEM);
        cudaFuncSetAttribute(lstm_persistent,
                             cudaFuncAttributeMaxDynamicSharedMemorySize, LSTM_SMEM);
        attr_set = true;
    }

    prep<<<(DD * G4 + 255) / 256, 256>>>(h0, Wx);
    xg_kernel<<<dim3(G4 / 64, (BB * TT) / 128), 256, XG_SMEM>>>(x, bias);
    lstm_persistent<<<NBLK, NTHR, LSTM_SMEM>>>(Wh, c0, (float*)d_out);
}